// round 2
// baseline (speedup 1.0000x reference)
#include <cuda_runtime.h>
#include <cuda_bf16.h>

#define N_NODES 100000
#define N_EDGES 3200000
#define F0 64
#define F1 128
#define F2 64

// Scratch (static __device__ arrays; no runtime allocation allowed)
__device__ float g_deg [N_NODES];
__device__ float g_dinv[N_NODES];
__device__ float g_hs  [N_NODES * F1];  // layer1: h*dinv[src]; later relu'd layer-1 output
__device__ float g_acc [N_NODES * F1];  // layer1 accumulator
__device__ float g_hs2 [N_NODES * F2];  // layer2: h2*dinv[src]

// ---------------------------------------------------------------------------
// Degree: init to 1 (self-loop), then count edge dst occurrences.
// ---------------------------------------------------------------------------
__global__ void k_deg_init() {
    int i = blockIdx.x * blockDim.x + threadIdx.x;
    if (i < N_NODES) g_deg[i] = 1.0f;
}

__global__ void k_deg_count(const int* __restrict__ dst) {
    int e = blockIdx.x * blockDim.x + threadIdx.x;
    if (e < N_EDGES) atomicAdd(&g_deg[dst[e]], 1.0f);
}

__global__ void k_dinv() {
    int i = blockIdx.x * blockDim.x + threadIdx.x;
    if (i < N_NODES) g_dinv[i] = rsqrtf(g_deg[i]);
}

// ---------------------------------------------------------------------------
// GEMM1: hs[i,j] = dinv[i] * sum_k x[i,k] * W1[k,j];  acc init = hs (self-loop)
// ---------------------------------------------------------------------------
__global__ void k_gemm1(const float* __restrict__ x, const float* __restrict__ W1) {
    __shared__ float W1s[F0 * F1];   // 32 KB
    __shared__ float xs[F0];
    int tid = threadIdx.x;           // 128 threads
    for (int i = tid; i < F0 * F1; i += 128) W1s[i] = W1[i];
    __syncthreads();

    for (int row = blockIdx.x; row < N_NODES; row += gridDim.x) {
        if (tid < F0) xs[tid] = x[row * F0 + tid];
        __syncthreads();
        float a = 0.0f;
        #pragma unroll
        for (int k = 0; k < F0; ++k) a = fmaf(xs[k], W1s[k * F1 + tid], a);
        float v = a * g_dinv[row];
        g_hs [row * F1 + tid] = v;
        g_acc[row * F1 + tid] = v;
        __syncthreads();
    }
}

// ---------------------------------------------------------------------------
// Scatter layer 1: one warp per edge, 4 floats per lane (128 features).
// acc[dst] += hs[src]
// ---------------------------------------------------------------------------
__global__ void k_scatter1(const int* __restrict__ src,
                           const int* __restrict__ dst) {
    int warps_per_block = blockDim.x >> 5;
    long long w = (long long)blockIdx.x * warps_per_block + (threadIdx.x >> 5);
    int lane = threadIdx.x & 31;
    long long total_warps = (long long)gridDim.x * warps_per_block;
    for (long long e = w; e < N_EDGES; e += total_warps) {
        int idx = (lane == 0) ? src[e] : ((lane == 1) ? dst[e] : 0);
        int s = __shfl_sync(0xffffffffu, idx, 0);
        int d = __shfl_sync(0xffffffffu, idx, 1);
        float4 v = *(const float4*)&g_hs[(long long)s * F1 + lane * 4];
        float* dp = &g_acc[(long long)d * F1 + lane * 4];
        atomicAdd(dp + 0, v.x);
        atomicAdd(dp + 1, v.y);
        atomicAdd(dp + 2, v.z);
        atomicAdd(dp + 3, v.w);
    }
}

// ---------------------------------------------------------------------------
// Finalize layer 1: h2 = relu(acc * dinv[i] + b1)   (written back into g_hs)
// ---------------------------------------------------------------------------
__global__ void k_finalize1(const float* __restrict__ b1) {
    long long idx = (long long)blockIdx.x * blockDim.x + threadIdx.x;
    if (idx < (long long)N_NODES * F1) {
        int i = (int)(idx >> 7);       // /128
        int j = (int)(idx & 127);
        float v = g_acc[idx] * g_dinv[i] + b1[j];
        g_hs[idx] = fmaxf(v, 0.0f);
    }
}

// ---------------------------------------------------------------------------
// GEMM2: hs2[i,j] = dinv[i] * sum_k h2[i,k] * W2[k,j]; out init = hs2
// ---------------------------------------------------------------------------
__global__ void k_gemm2(const float* __restrict__ W2, float* __restrict__ out) {
    __shared__ float W2s[F1 * F2];       // 32 KB
    __shared__ float xs[4 * F1];         // 2 KB
    int tid = threadIdx.x;               // 256 threads
    for (int i = tid; i < F1 * F2; i += 256) W2s[i] = W2[i];
    __syncthreads();

    int sub = tid >> 6;      // 0..3
    int j   = tid & 63;

    for (int r0 = blockIdx.x * 4; r0 < N_NODES; r0 += gridDim.x * 4) {
        for (int t = tid; t < 4 * F1; t += 256) {
            int rr = r0 + (t >> 7);
            xs[t] = (rr < N_NODES) ? g_hs[(long long)rr * F1 + (t & 127)] : 0.0f;
        }
        __syncthreads();
        int row = r0 + sub;
        if (row < N_NODES) {
            float a = 0.0f;
            #pragma unroll
            for (int k = 0; k < F1; ++k) a = fmaf(xs[sub * F1 + k], W2s[k * F2 + j], a);
            float v = a * g_dinv[row];
            g_hs2[(long long)row * F2 + j] = v;
            out  [(long long)row * F2 + j] = v;   // self-loop init
        }
        __syncthreads();
    }
}

// ---------------------------------------------------------------------------
// Scatter layer 2: warp per edge, 2 floats per lane (64 features).
// out[dst] += hs2[src]
// ---------------------------------------------------------------------------
__global__ void k_scatter2(const int* __restrict__ src,
                           const int* __restrict__ dst,
                           float* __restrict__ out) {
    int warps_per_block = blockDim.x >> 5;
    long long w = (long long)blockIdx.x * warps_per_block + (threadIdx.x >> 5);
    int lane = threadIdx.x & 31;
    long long total_warps = (long long)gridDim.x * warps_per_block;
    for (long long e = w; e < N_EDGES; e += total_warps) {
        int idx = (lane == 0) ? src[e] : ((lane == 1) ? dst[e] : 0);
        int s = __shfl_sync(0xffffffffu, idx, 0);
        int d = __shfl_sync(0xffffffffu, idx, 1);
        float2 v = *(const float2*)&g_hs2[(long long)s * F2 + lane * 2];
        float* dp = &out[(long long)d * F2 + lane * 2];
        atomicAdd(dp + 0, v.x);
        atomicAdd(dp + 1, v.y);
    }
}

// ---------------------------------------------------------------------------
// Finalize layer 2: out = out * dinv[i] + b2  (no relu)
// ---------------------------------------------------------------------------
__global__ void k_finalize2(const float* __restrict__ b2, float* __restrict__ out) {
    long long idx = (long long)blockIdx.x * blockDim.x + threadIdx.x;
    if (idx < (long long)N_NODES * F2) {
        int i = (int)(idx >> 6);        // /64
        int j = (int)(idx & 63);
        out[idx] = out[idx] * g_dinv[i] + b2[j];
    }
}

// ---------------------------------------------------------------------------
extern "C" void kernel_launch(void* const* d_in, const int* in_sizes, int n_in,
                              void* d_out, int out_size) {
    const float* x   = (const float*)d_in[0];
    const int*   ei  = (const int*)d_in[1];   // [2, E] — JAX default x64-disabled => int32
    const float* W1  = (const float*)d_in[2];
    const float* b1  = (const float*)d_in[3];
    const float* W2  = (const float*)d_in[4];
    const float* b2  = (const float*)d_in[5];
    float*       out = (float*)d_out;

    const int* src = ei;
    const int* dst = ei + N_EDGES;

    // degree + dinv
    k_deg_init <<<(N_NODES + 255) / 256, 256>>>();
    k_deg_count<<<(N_EDGES + 255) / 256, 256>>>(dst);
    k_dinv     <<<(N_NODES + 255) / 256, 256>>>();

    // layer 1
    k_gemm1<<<2048, 128>>>(x, W1);
    {
        int tpb = 256;                       // 8 warps/block
        int blocks = (N_EDGES + 7) / 8;      // one warp per edge
        k_scatter1<<<blocks, tpb>>>(src, dst);
    }
    {
        long long total = (long long)N_NODES * F1;
        k_finalize1<<<(int)((total + 255) / 256), 256>>>(b1);
    }

    // layer 2
    k_gemm2<<<2048, 256>>>(W2, out);
    {
        int tpb = 256;
        int blocks = (N_EDGES + 7) / 8;
        k_scatter2<<<blocks, tpb>>>(src, dst, out);
    }
    {
        long long total = (long long)N_NODES * F2;
        k_finalize2<<<(int)((total + 255) / 256), 256>>>(b2, out);
    }
}

// round 3
// speedup vs baseline: 2.4084x; 2.4084x over previous
#include <cuda_runtime.h>
#include <cuda_bf16.h>

#define N_NODES 100000
#define N_EDGES 3200000
#define F0 64
#define F1 128
#define F2 64

// Scratch (static __device__ arrays; no runtime allocation allowed)
__device__ float g_deg [N_NODES];
__device__ float g_dinv[N_NODES];
__device__ float g_hs  [N_NODES * F1];  // layer1: h*dinv[src]; later relu'd layer-1 output
__device__ float g_acc [N_NODES * F1];  // layer1 accumulator
__device__ float g_hs2 [N_NODES * F2];  // layer2: h2*dinv[src]

// ---------------------------------------------------------------------------
// Degree: init to 1 (self-loop), count edge dst, then rsqrt.
// ---------------------------------------------------------------------------
__global__ void k_deg_init() {
    int i = blockIdx.x * blockDim.x + threadIdx.x;
    if (i < N_NODES) g_deg[i] = 1.0f;
}

__global__ void k_deg_count(const int* __restrict__ dst) {
    int e = blockIdx.x * blockDim.x + threadIdx.x;
    if (e < N_EDGES) atomicAdd(&g_deg[dst[e]], 1.0f);
}

__global__ void k_dinv() {
    int i = blockIdx.x * blockDim.x + threadIdx.x;
    if (i < N_NODES) g_dinv[i] = rsqrtf(g_deg[i]);
}

// ---------------------------------------------------------------------------
// GEMM1: hs[i,j] = dinv[i] * sum_k x[i,k] * W1[k,j];  acc init = hs (self-loop)
// 128 threads (one per output col), 8 rows per iteration, register-blocked.
// ---------------------------------------------------------------------------
#define R1 8
__global__ void k_gemm1(const float* __restrict__ x, const float* __restrict__ W1) {
    __shared__ float W1s[F0 * F1];   // 32 KB
    __shared__ float xs[R1 * F0];    // 2 KB
    int tid = threadIdx.x;           // 128 threads
    for (int i = tid; i < F0 * F1; i += 128) W1s[i] = W1[i];
    __syncthreads();

    for (int r0 = blockIdx.x * R1; r0 < N_NODES; r0 += gridDim.x * R1) {
        int nrows = min(R1, N_NODES - r0);
        // 8 rows x 64 floats = 128 float4: one per thread, coalesced
        {
            int r = tid >> 4;            // 16 float4 per row
            int c = (tid & 15) * 4;
            if (r < nrows)
                *(float4*)&xs[r * F0 + c] = *(const float4*)&x[(size_t)(r0 + r) * F0 + c];
        }
        __syncthreads();

        float acc[R1];
        #pragma unroll
        for (int r = 0; r < R1; ++r) acc[r] = 0.0f;

        #pragma unroll
        for (int k = 0; k < F0; k += 4) {
            float w0 = W1s[(k + 0) * F1 + tid];
            float w1 = W1s[(k + 1) * F1 + tid];
            float w2 = W1s[(k + 2) * F1 + tid];
            float w3 = W1s[(k + 3) * F1 + tid];
            #pragma unroll
            for (int r = 0; r < R1; ++r) {
                float4 xv = *(const float4*)&xs[r * F0 + k];
                acc[r] = fmaf(xv.x, w0, fmaf(xv.y, w1, fmaf(xv.z, w2, fmaf(xv.w, w3, acc[r]))));
            }
        }

        #pragma unroll
        for (int r = 0; r < R1; ++r) {
            if (r < nrows) {
                float v = acc[r] * g_dinv[r0 + r];
                g_hs [(size_t)(r0 + r) * F1 + tid] = v;
                g_acc[(size_t)(r0 + r) * F1 + tid] = v;
            }
        }
        __syncthreads();
    }
}

// ---------------------------------------------------------------------------
// Scatter layer 1: warp batches 32 edges (coalesced index loads), then per
// edge each lane moves 4 floats via one vector reduction: acc[dst] += hs[src].
// ---------------------------------------------------------------------------
__global__ void k_scatter1(const int* __restrict__ src,
                           const int* __restrict__ dst) {
    int lane = threadIdx.x & 31;
    int warp = blockIdx.x * (blockDim.x >> 5) + (threadIdx.x >> 5);
    int nwarp = gridDim.x * (blockDim.x >> 5);
    for (int base = warp * 32; base < N_EDGES; base += nwarp * 32) {
        int s = src[base + lane];
        int d = dst[base + lane];
        #pragma unroll 4
        for (int i = 0; i < 32; ++i) {
            int ss = __shfl_sync(0xffffffffu, s, i);
            int dd = __shfl_sync(0xffffffffu, d, i);
            float4 v = *(const float4*)&g_hs[(size_t)ss * F1 + lane * 4];
            float* dp = &g_acc[(size_t)dd * F1 + lane * 4];
            asm volatile("red.global.add.v4.f32 [%0], {%1, %2, %3, %4};"
                         :: "l"(dp), "f"(v.x), "f"(v.y), "f"(v.z), "f"(v.w)
                         : "memory");
        }
    }
}

// ---------------------------------------------------------------------------
// Finalize layer 1: h2 = relu(acc * dinv[i] + b1), vectorized float4.
// ---------------------------------------------------------------------------
__global__ void k_finalize1(const float* __restrict__ b1) {
    int idx = blockIdx.x * blockDim.x + threadIdx.x;     // one float4 each
    if (idx < N_NODES * F1 / 4) {
        int i  = idx >> 5;                               // 32 float4 per row
        int j4 = (idx & 31) * 4;
        float di = g_dinv[i];
        float4 a = *(const float4*)&g_acc[(size_t)idx * 4];
        float4 b = *(const float4*)&b1[j4];
        float4 o;
        o.x = fmaxf(fmaf(a.x, di, b.x), 0.0f);
        o.y = fmaxf(fmaf(a.y, di, b.y), 0.0f);
        o.z = fmaxf(fmaf(a.z, di, b.z), 0.0f);
        o.w = fmaxf(fmaf(a.w, di, b.w), 0.0f);
        *(float4*)&g_hs[(size_t)idx * 4] = o;
    }
}

// ---------------------------------------------------------------------------
// GEMM2: hs2[i,j] = dinv[i] * sum_k h2[i,k] * W2[k,j]; out init = hs2.
// 128 threads: j = tid&63, half = tid>>6; 8 rows/iter, 4 per half.
// ---------------------------------------------------------------------------
__global__ void k_gemm2(const float* __restrict__ W2, float* __restrict__ out) {
    __shared__ float W2s[F1 * F2];       // 32 KB
    __shared__ float xs[8 * F1];         // 4 KB
    int tid = threadIdx.x;               // 128 threads
    for (int i = tid; i < F1 * F2; i += 128) W2s[i] = W2[i];
    __syncthreads();

    int j    = tid & 63;
    int half = tid >> 6;

    for (int r0 = blockIdx.x * 8; r0 < N_NODES; r0 += gridDim.x * 8) {
        int nrows = min(8, N_NODES - r0);
        // 8 rows x 128 floats = 256 float4: 2 per thread, coalesced
        #pragma unroll
        for (int t = 0; t < 2; ++t) {
            int f4 = tid + t * 128;      // float4 index 0..255
            int r  = f4 >> 5;            // 32 float4 per row
            int c  = (f4 & 31) * 4;
            if (r < nrows)
                *(float4*)&xs[r * F1 + c] = *(const float4*)&g_hs[(size_t)(r0 + r) * F1 + c];
        }
        __syncthreads();

        float acc[4] = {0.f, 0.f, 0.f, 0.f};
        #pragma unroll 8
        for (int k = 0; k < F1; k += 4) {
            float w0 = W2s[(k + 0) * F2 + j];
            float w1 = W2s[(k + 1) * F2 + j];
            float w2 = W2s[(k + 2) * F2 + j];
            float w3 = W2s[(k + 3) * F2 + j];
            #pragma unroll
            for (int r = 0; r < 4; ++r) {
                float4 xv = *(const float4*)&xs[(half * 4 + r) * F1 + k];
                acc[r] = fmaf(xv.x, w0, fmaf(xv.y, w1, fmaf(xv.z, w2, fmaf(xv.w, w3, acc[r]))));
            }
        }

        #pragma unroll
        for (int r = 0; r < 4; ++r) {
            int row = r0 + half * 4 + r;
            if (row < N_NODES) {
                float v = acc[r] * g_dinv[row];
                g_hs2[(size_t)row * F2 + j] = v;
                out  [(size_t)row * F2 + j] = v;   // self-loop init
            }
        }
        __syncthreads();
    }
}

// ---------------------------------------------------------------------------
// Scatter layer 2: warp batches 32 edges, per edge one red.v2 per lane.
// out[dst] += hs2[src]
// ---------------------------------------------------------------------------
__global__ void k_scatter2(const int* __restrict__ src,
                           const int* __restrict__ dst,
                           float* __restrict__ out) {
    int lane = threadIdx.x & 31;
    int warp = blockIdx.x * (blockDim.x >> 5) + (threadIdx.x >> 5);
    int nwarp = gridDim.x * (blockDim.x >> 5);
    for (int base = warp * 32; base < N_EDGES; base += nwarp * 32) {
        int s = src[base + lane];
        int d = dst[base + lane];
        #pragma unroll 4
        for (int i = 0; i < 32; ++i) {
            int ss = __shfl_sync(0xffffffffu, s, i);
            int dd = __shfl_sync(0xffffffffu, d, i);
            float2 v = *(const float2*)&g_hs2[(size_t)ss * F2 + lane * 2];
            float* dp = &out[(size_t)dd * F2 + lane * 2];
            asm volatile("red.global.add.v2.f32 [%0], {%1, %2};"
                         :: "l"(dp), "f"(v.x), "f"(v.y)
                         : "memory");
        }
    }
}

// ---------------------------------------------------------------------------
// Finalize layer 2: out = out * dinv[i] + b2, vectorized float4.
// ---------------------------------------------------------------------------
__global__ void k_finalize2(const float* __restrict__ b2, float* __restrict__ out) {
    int idx = blockIdx.x * blockDim.x + threadIdx.x;
    if (idx < N_NODES * F2 / 4) {
        int i  = idx >> 4;               // 16 float4 per row
        int j4 = (idx & 15) * 4;
        float di = g_dinv[i];
        float4 a = *(const float4*)((const float*)out + (size_t)idx * 4);
        float4 b = *(const float4*)&b2[j4];
        float4 o;
        o.x = fmaf(a.x, di, b.x);
        o.y = fmaf(a.y, di, b.y);
        o.z = fmaf(a.z, di, b.z);
        o.w = fmaf(a.w, di, b.w);
        *(float4*)((float*)out + (size_t)idx * 4) = o;
    }
}

// ---------------------------------------------------------------------------
extern "C" void kernel_launch(void* const* d_in, const int* in_sizes, int n_in,
                              void* d_out, int out_size) {
    const float* x   = (const float*)d_in[0];
    const int*   ei  = (const int*)d_in[1];   // [2, E] int32 (JAX x64 disabled)
    const float* W1  = (const float*)d_in[2];
    const float* b1  = (const float*)d_in[3];
    const float* W2  = (const float*)d_in[4];
    const float* b2  = (const float*)d_in[5];
    float*       out = (float*)d_out;

    const int* src = ei;
    const int* dst = ei + N_EDGES;

    // degree + dinv
    k_deg_init <<<(N_NODES + 255) / 256, 256>>>();
    k_deg_count<<<(N_EDGES + 255) / 256, 256>>>(dst);
    k_dinv     <<<(N_NODES + 255) / 256, 256>>>();

    // layer 1
    k_gemm1<<<(N_NODES + R1 - 1) / R1, 128>>>(x, W1);
    {
        // 100000 edge-groups of 32; 8 warps per block
        int nwarps = N_EDGES / 32;                    // 100000
        k_scatter1<<<(nwarps + 7) / 8, 256>>>(src, dst);
    }
    k_finalize1<<<(N_NODES * F1 / 4 + 255) / 256, 256>>>(b1);

    // layer 2
    k_gemm2<<<(N_NODES + 7) / 8, 128>>>(W2, out);
    {
        int nwarps = N_EDGES / 32;
        k_scatter2<<<(nwarps + 7) / 8, 256>>>(src, dst, out);
    }
    k_finalize2<<<(N_NODES * F2 / 4 + 255) / 256, 256>>>(b2, out);
}

// round 4
// speedup vs baseline: 4.1683x; 1.7307x over previous
#include <cuda_runtime.h>
#include <cuda_bf16.h>

#define N_NODES 100000
#define N_EDGES 3200000
#define F0 64
#define F1 128
#define F2 64
#define N_CHUNKS 98   // ceil(100000/1024)

// Scratch (static __device__ arrays)
__device__ int   g_degi[N_NODES];
__device__ int   g_scan[N_NODES];
__device__ int   g_chunksum[N_CHUNKS];
__device__ int   g_chunkoff[N_CHUNKS];
__device__ int   g_row [N_NODES + 1];
__device__ int   g_cur [N_NODES];
__device__ int   g_csr [N_EDGES];
__device__ float g_dinv[N_NODES];
__device__ float g_hs  [N_NODES * F1];  // layer1 pre-scaled: (x@W1)*dinv
__device__ float g_h2  [N_NODES * F1];  // relu'd layer-1 output
__device__ float g_hs2 [N_NODES * F2];  // layer2 pre-scaled: (h2@W2)*dinv

// ---------------------------------------------------------------------------
// Degree histogram (int), dinv includes self-loop (+1).
// ---------------------------------------------------------------------------
__global__ void k_deg_zero() {
    int i = blockIdx.x * blockDim.x + threadIdx.x;
    if (i < N_NODES) g_degi[i] = 0;
}

__global__ void k_deg_count(const int* __restrict__ dst) {
    int e = blockIdx.x * blockDim.x + threadIdx.x;
    if (e < N_EDGES) atomicAdd(&g_degi[dst[e]], 1);
}

__global__ void k_dinv() {
    int i = blockIdx.x * blockDim.x + threadIdx.x;
    if (i < N_NODES) g_dinv[i] = rsqrtf((float)(g_degi[i] + 1));
}

// ---------------------------------------------------------------------------
// Prefix-sum (3 kernels) -> row_ptr (exclusive), then CSR fill.
// ---------------------------------------------------------------------------
__global__ void k_scan_chunk() {   // grid N_CHUNKS, block 1024
    __shared__ int sh[1024];
    int gid = blockIdx.x * 1024 + threadIdx.x;
    int v = (gid < N_NODES) ? g_degi[gid] : 0;
    sh[threadIdx.x] = v;
    __syncthreads();
    #pragma unroll
    for (int off = 1; off < 1024; off <<= 1) {
        int t = (threadIdx.x >= off) ? sh[threadIdx.x - off] : 0;
        __syncthreads();
        sh[threadIdx.x] += t;
        __syncthreads();
    }
    if (gid < N_NODES) g_scan[gid] = sh[threadIdx.x];     // inclusive
    if (threadIdx.x == 1023) g_chunksum[blockIdx.x] = sh[1023];
}

__global__ void k_scan_sums() {    // 1 block, 128 threads
    __shared__ int sh[128];
    int tid = threadIdx.x;
    int v = (tid < N_CHUNKS) ? g_chunksum[tid] : 0;
    sh[tid] = v;
    __syncthreads();
    #pragma unroll
    for (int off = 1; off < 128; off <<= 1) {
        int t = (tid >= off) ? sh[tid - off] : 0;
        __syncthreads();
        sh[tid] += t;
        __syncthreads();
    }
    if (tid < N_CHUNKS) g_chunkoff[tid] = sh[tid] - v;    // exclusive
}

__global__ void k_row_ptr() {      // grid covers N_NODES
    int i = blockIdx.x * blockDim.x + threadIdx.x;
    if (i < N_NODES) {
        int r = g_scan[i] - g_degi[i] + g_chunkoff[i >> 10];
        g_row[i] = r;
        g_cur[i] = r;
    }
    if (i == 0) g_row[N_NODES] = N_EDGES;
}

__global__ void k_csr_fill(const int* __restrict__ src, const int* __restrict__ dst) {
    int e = blockIdx.x * blockDim.x + threadIdx.x;
    if (e < N_EDGES) {
        int pos = atomicAdd(&g_cur[dst[e]], 1);
        g_csr[pos] = src[e];
    }
}

// ---------------------------------------------------------------------------
// GEMM1: hs[i,j] = dinv[i] * sum_k x[i,k]*W1[k,j].  256 thr, 16 rows/tile.
// ---------------------------------------------------------------------------
__global__ void k_gemm1(const float* __restrict__ x, const float* __restrict__ W1) {
    __shared__ float W1s[F0 * F1];   // 32 KB
    __shared__ float xs[16 * F0];    // 4 KB
    int tid = threadIdx.x;           // 256
    for (int i = tid; i < F0 * F1; i += 256) W1s[i] = W1[i];
    __syncthreads();

    int col = tid & 127;
    int rh  = tid >> 7;              // 0/1 -> rows rh*8 .. rh*8+7

    int r0 = blockIdx.x * 16;        // 100000/16 = 6250 exact
    {
        // 16 rows x 16 float4 = 256 float4: one per thread
        int r = tid >> 4;
        int c = (tid & 15) * 4;
        *(float4*)&xs[r * F0 + c] = *(const float4*)&x[(size_t)(r0 + r) * F0 + c];
    }
    __syncthreads();

    float acc[8];
    #pragma unroll
    for (int r = 0; r < 8; ++r) acc[r] = 0.0f;

    #pragma unroll
    for (int k = 0; k < F0; k += 4) {
        float w0 = W1s[(k + 0) * F1 + col];
        float w1 = W1s[(k + 1) * F1 + col];
        float w2 = W1s[(k + 2) * F1 + col];
        float w3 = W1s[(k + 3) * F1 + col];
        #pragma unroll
        for (int r = 0; r < 8; ++r) {
            float4 xv = *(const float4*)&xs[(rh * 8 + r) * F0 + k];
            acc[r] = fmaf(xv.x, w0, fmaf(xv.y, w1, fmaf(xv.z, w2, fmaf(xv.w, w3, acc[r]))));
        }
    }

    #pragma unroll
    for (int r = 0; r < 8; ++r) {
        int row = r0 + rh * 8 + r;
        g_hs[(size_t)row * F1 + col] = acc[r] * g_dinv[row];
    }
}

// ---------------------------------------------------------------------------
// Pull layer 1: warp per node. h2 = relu((hs[i] + sum_in hs[s]) * dinv + b1)
// ---------------------------------------------------------------------------
__global__ void k_pull1(const float* __restrict__ b1) {
    int lane = threadIdx.x & 31;
    int warp = blockIdx.x * (blockDim.x >> 5) + (threadIdx.x >> 5);
    int nwarp = gridDim.x * (blockDim.x >> 5);
    float4 bb = *(const float4*)&b1[lane * 4];
    for (int node = warp; node < N_NODES; node += nwarp) {
        int beg = g_row[node], end = g_row[node + 1];
        float4 acc = *(const float4*)&g_hs[(size_t)node * F1 + lane * 4];  // self-loop
        for (int e0 = beg; e0 < end; e0 += 32) {
            int n = end - e0;
            int s = (lane < n) ? g_csr[e0 + lane] : 0;
            int cnt = min(n, 32);
            for (int i = 0; i < cnt; ++i) {
                int ss = __shfl_sync(0xffffffffu, s, i);
                float4 v = *(const float4*)&g_hs[(size_t)ss * F1 + lane * 4];
                acc.x += v.x; acc.y += v.y; acc.z += v.z; acc.w += v.w;
            }
        }
        float di = g_dinv[node];
        float4 o;
        o.x = fmaxf(fmaf(acc.x, di, bb.x), 0.0f);
        o.y = fmaxf(fmaf(acc.y, di, bb.y), 0.0f);
        o.z = fmaxf(fmaf(acc.z, di, bb.z), 0.0f);
        o.w = fmaxf(fmaf(acc.w, di, bb.w), 0.0f);
        *(float4*)&g_h2[(size_t)node * F1 + lane * 4] = o;
    }
}

// ---------------------------------------------------------------------------
// GEMM2: hs2[i,j] = dinv[i] * sum_k h2[i,k]*W2[k,j].  256 thr, 16 rows/tile.
// ---------------------------------------------------------------------------
__global__ void k_gemm2(const float* __restrict__ W2) {
    __shared__ float W2s[F1 * F2];       // 32 KB
    __shared__ float xs[16 * F1];        // 8 KB
    int tid = threadIdx.x;               // 256
    for (int i = tid; i < F1 * F2; i += 256) W2s[i] = W2[i];
    __syncthreads();

    int j = tid & 63;
    int q = tid >> 6;                    // 0..3 -> rows q*4 .. q*4+3

    int r0 = blockIdx.x * 16;            // 6250 exact
    #pragma unroll
    for (int t = 0; t < 2; ++t) {
        int f4 = tid + t * 256;          // 0..511
        int r  = f4 >> 5;                // 32 float4 per row
        int c  = (f4 & 31) * 4;
        *(float4*)&xs[r * F1 + c] = *(const float4*)&g_h2[(size_t)(r0 + r) * F1 + c];
    }
    __syncthreads();

    float acc[4] = {0.f, 0.f, 0.f, 0.f};
    #pragma unroll 8
    for (int k = 0; k < F1; k += 4) {
        float w0 = W2s[(k + 0) * F2 + j];
        float w1 = W2s[(k + 1) * F2 + j];
        float w2 = W2s[(k + 2) * F2 + j];
        float w3 = W2s[(k + 3) * F2 + j];
        #pragma unroll
        for (int r = 0; r < 4; ++r) {
            float4 xv = *(const float4*)&xs[(q * 4 + r) * F1 + k];
            acc[r] = fmaf(xv.x, w0, fmaf(xv.y, w1, fmaf(xv.z, w2, fmaf(xv.w, w3, acc[r]))));
        }
    }

    #pragma unroll
    for (int r = 0; r < 4; ++r) {
        int row = r0 + q * 4 + r;
        g_hs2[(size_t)row * F2 + j] = acc[r] * g_dinv[row];
    }
}

// ---------------------------------------------------------------------------
// Pull layer 2: half-warp per node. out = (hs2[i] + sum_in hs2[s])*dinv + b2
// ---------------------------------------------------------------------------
__global__ void k_pull2(const float* __restrict__ b2, float* __restrict__ out) {
    int lane = threadIdx.x & 31;
    int sub  = lane & 15;
    int half = lane >> 4;
    unsigned hmask = 0xFFFFu << (half * 16);
    int warp = blockIdx.x * (blockDim.x >> 5) + (threadIdx.x >> 5);
    int nwarp = gridDim.x * (blockDim.x >> 5);
    float4 bb = *(const float4*)&b2[sub * 4];
    for (int node = warp * 2 + half; node < N_NODES; node += nwarp * 2) {
        int beg = g_row[node], end = g_row[node + 1];
        float4 acc = *(const float4*)&g_hs2[(size_t)node * F2 + sub * 4];  // self-loop
        for (int e0 = beg; e0 < end; e0 += 16) {
            int n = end - e0;
            int s = (sub < n) ? g_csr[e0 + sub] : 0;
            int cnt = min(n, 16);
            for (int i = 0; i < cnt; ++i) {
                int ss = __shfl_sync(hmask, s, i, 16);
                float4 v = *(const float4*)&g_hs2[(size_t)ss * F2 + sub * 4];
                acc.x += v.x; acc.y += v.y; acc.z += v.z; acc.w += v.w;
            }
        }
        float di = g_dinv[node];
        float4 o;
        o.x = fmaf(acc.x, di, bb.x);
        o.y = fmaf(acc.y, di, bb.y);
        o.z = fmaf(acc.z, di, bb.z);
        o.w = fmaf(acc.w, di, bb.w);
        *(float4*)&out[(size_t)node * F2 + sub * 4] = o;
    }
}

// ---------------------------------------------------------------------------
extern "C" void kernel_launch(void* const* d_in, const int* in_sizes, int n_in,
                              void* d_out, int out_size) {
    const float* x   = (const float*)d_in[0];
    const int*   ei  = (const int*)d_in[1];   // [2, E] int32
    const float* W1  = (const float*)d_in[2];
    const float* b1  = (const float*)d_in[3];
    const float* W2  = (const float*)d_in[4];
    const float* b2  = (const float*)d_in[5];
    float*       out = (float*)d_out;

    const int* src = ei;
    const int* dst = ei + N_EDGES;

    // degree + dinv + CSR
    k_deg_zero <<<(N_NODES + 255) / 256, 256>>>();
    k_deg_count<<<(N_EDGES + 255) / 256, 256>>>(dst);
    k_dinv     <<<(N_NODES + 255) / 256, 256>>>();
    k_scan_chunk<<<N_CHUNKS, 1024>>>();
    k_scan_sums<<<1, 128>>>();
    k_row_ptr  <<<(N_NODES + 255) / 256, 256>>>();
    k_csr_fill <<<(N_EDGES + 255) / 256, 256>>>(src, dst);

    // layer 1
    k_gemm1<<<N_NODES / 16, 256>>>(x, W1);
    k_pull1<<<(N_NODES + 7) / 8, 256>>>(b1);          // 1 warp/node, 8 warps/block

    // layer 2
    k_gemm2<<<N_NODES / 16, 256>>>(W2);
    k_pull2<<<(N_NODES / 2 + 7) / 8, 256>>>(b2, out); // 2 nodes/warp
}

// round 5
// speedup vs baseline: 4.7901x; 1.1492x over previous
#include <cuda_runtime.h>
#include <cuda_bf16.h>

#define N_NODES 100000
#define N_EDGES 3200000
#define F0 64
#define F1 128
#define F2 64
#define N_CHUNKS 98   // ceil(100000/1024)

// Scratch (static __device__ arrays)
__device__ int   g_degi[N_NODES];
__device__ int   g_scan[N_NODES];
__device__ int   g_chunksum[N_CHUNKS];
__device__ int   g_chunkoff[N_CHUNKS];
__device__ int   g_row [N_NODES + 1];
__device__ int   g_cur [N_NODES];
__device__ int   g_csr [N_EDGES];
__device__ float g_dinv[N_NODES];
__device__ float g_xs  [N_NODES * F0];  // x * dinv[node]  (pre-scaled input)
__device__ float g_ag  [N_NODES * F0];  // aggregated input-space features
__device__ float g_h2  [N_NODES * F1];  // relu'd layer-1 output
__device__ float g_hs2 [N_NODES * F2];  // (h2@W2) * dinv

// ---------------------------------------------------------------------------
// Degree histogram (int), dinv includes self-loop (+1).
// ---------------------------------------------------------------------------
__global__ void k_deg_zero() {
    int i = blockIdx.x * blockDim.x + threadIdx.x;
    if (i < N_NODES) g_degi[i] = 0;
}

__global__ void k_deg_count(const int* __restrict__ dst) {
    int e = blockIdx.x * blockDim.x + threadIdx.x;
    if (e < N_EDGES) atomicAdd(&g_degi[dst[e]], 1);
}

__global__ void k_dinv() {
    int i = blockIdx.x * blockDim.x + threadIdx.x;
    if (i < N_NODES) g_dinv[i] = rsqrtf((float)(g_degi[i] + 1));
}

// ---------------------------------------------------------------------------
// Prefix-sum -> row_ptr (exclusive), then CSR fill (by dst, storing src).
// ---------------------------------------------------------------------------
__global__ void k_scan_chunk() {   // grid N_CHUNKS, block 1024
    __shared__ int sh[1024];
    int gid = blockIdx.x * 1024 + threadIdx.x;
    int v = (gid < N_NODES) ? g_degi[gid] : 0;
    sh[threadIdx.x] = v;
    __syncthreads();
    #pragma unroll
    for (int off = 1; off < 1024; off <<= 1) {
        int t = (threadIdx.x >= off) ? sh[threadIdx.x - off] : 0;
        __syncthreads();
        sh[threadIdx.x] += t;
        __syncthreads();
    }
    if (gid < N_NODES) g_scan[gid] = sh[threadIdx.x];     // inclusive
    if (threadIdx.x == 1023) g_chunksum[blockIdx.x] = sh[1023];
}

__global__ void k_scan_sums() {    // 1 block, 128 threads
    __shared__ int sh[128];
    int tid = threadIdx.x;
    int v = (tid < N_CHUNKS) ? g_chunksum[tid] : 0;
    sh[tid] = v;
    __syncthreads();
    #pragma unroll
    for (int off = 1; off < 128; off <<= 1) {
        int t = (tid >= off) ? sh[tid - off] : 0;
        __syncthreads();
        sh[tid] += t;
        __syncthreads();
    }
    if (tid < N_CHUNKS) g_chunkoff[tid] = sh[tid] - v;    // exclusive
}

__global__ void k_row_ptr() {
    int i = blockIdx.x * blockDim.x + threadIdx.x;
    if (i < N_NODES) {
        int r = g_scan[i] - g_degi[i] + g_chunkoff[i >> 10];
        g_row[i] = r;
        g_cur[i] = r;
    }
    if (i == 0) g_row[N_NODES] = N_EDGES;
}

__global__ void k_csr_fill(const int* __restrict__ src, const int* __restrict__ dst) {
    int e = blockIdx.x * blockDim.x + threadIdx.x;
    if (e < N_EDGES) {
        int pos = atomicAdd(&g_cur[dst[e]], 1);
        g_csr[pos] = src[e];
    }
}

// ---------------------------------------------------------------------------
// Pre-scale: xs = x * dinv[node]
// ---------------------------------------------------------------------------
__global__ void k_prescale(const float* __restrict__ x) {
    int idx = blockIdx.x * blockDim.x + threadIdx.x;   // one float4 each
    if (idx < N_NODES * F0 / 4) {
        int i = idx >> 4;                              // 16 float4 per row
        float di = g_dinv[i];
        float4 a = *(const float4*)&x[(size_t)idx * 4];
        a.x *= di; a.y *= di; a.z *= di; a.w *= di;
        *(float4*)&g_xs[(size_t)idx * 4] = a;
    }
}

// ---------------------------------------------------------------------------
// Pull in 64-dim: half-warp per node, 4x unrolled gathers for MLP.
//   ag[node] = (xs[node] + sum_in xs[s]) * dinv[node]
// ---------------------------------------------------------------------------
__device__ __forceinline__ float4 pull64(const float* __restrict__ feat,
                                         int node, int sub, unsigned hmask) {
    int beg = g_row[node], end = g_row[node + 1];
    float4 acc = *(const float4*)&feat[(size_t)node * 64 + sub * 4];  // self-loop
    for (int e0 = beg; e0 < end; e0 += 16) {
        int n = end - e0;
        int s = (sub < n) ? g_csr[e0 + sub] : 0;
        int cnt = min(n, 16);
        int i = 0;
        for (; i + 4 <= cnt; i += 4) {
            int s0 = __shfl_sync(hmask, s, i + 0, 16);
            int s1 = __shfl_sync(hmask, s, i + 1, 16);
            int s2 = __shfl_sync(hmask, s, i + 2, 16);
            int s3 = __shfl_sync(hmask, s, i + 3, 16);
            float4 v0 = *(const float4*)&feat[(size_t)s0 * 64 + sub * 4];
            float4 v1 = *(const float4*)&feat[(size_t)s1 * 64 + sub * 4];
            float4 v2 = *(const float4*)&feat[(size_t)s2 * 64 + sub * 4];
            float4 v3 = *(const float4*)&feat[(size_t)s3 * 64 + sub * 4];
            acc.x += (v0.x + v1.x) + (v2.x + v3.x);
            acc.y += (v0.y + v1.y) + (v2.y + v3.y);
            acc.z += (v0.z + v1.z) + (v2.z + v3.z);
            acc.w += (v0.w + v1.w) + (v2.w + v3.w);
        }
        for (; i < cnt; ++i) {
            int ss = __shfl_sync(hmask, s, i, 16);
            float4 v = *(const float4*)&feat[(size_t)ss * 64 + sub * 4];
            acc.x += v.x; acc.y += v.y; acc.z += v.z; acc.w += v.w;
        }
    }
    return acc;
}

__global__ void k_pull1() {
    int lane = threadIdx.x & 31;
    int sub  = lane & 15;
    int half = lane >> 4;
    unsigned hmask = 0xFFFFu << (half * 16);
    int hw = (blockIdx.x * blockDim.x + threadIdx.x) >> 4;   // half-warp id
    int node = hw;
    if (node >= N_NODES) return;
    float4 acc = pull64(g_xs, node, sub, hmask);
    float di = g_dinv[node];
    acc.x *= di; acc.y *= di; acc.z *= di; acc.w *= di;
    *(float4*)&g_ag[(size_t)node * F0 + sub * 4] = acc;
}

__global__ void k_pull2(const float* __restrict__ b2, float* __restrict__ out) {
    int lane = threadIdx.x & 31;
    int sub  = lane & 15;
    int half = lane >> 4;
    unsigned hmask = 0xFFFFu << (half * 16);
    int hw = (blockIdx.x * blockDim.x + threadIdx.x) >> 4;
    int node = hw;
    if (node >= N_NODES) return;
    float4 acc = pull64(g_hs2, node, sub, hmask);
    float di = g_dinv[node];
    float4 bb = *(const float4*)&b2[sub * 4];
    float4 o;
    o.x = fmaf(acc.x, di, bb.x);
    o.y = fmaf(acc.y, di, bb.y);
    o.z = fmaf(acc.z, di, bb.z);
    o.w = fmaf(acc.w, di, bb.w);
    *(float4*)&out[(size_t)node * F2 + sub * 4] = o;
}

// ---------------------------------------------------------------------------
// GEMM1: h2 = relu(ag @ W1 + b1).  256 thr, 16 rows/tile.
// ---------------------------------------------------------------------------
__global__ void k_gemm1(const float* __restrict__ W1, const float* __restrict__ b1) {
    __shared__ float W1s[F0 * F1];   // 32 KB
    __shared__ float xs[16 * F0];    // 4 KB
    int tid = threadIdx.x;           // 256
    for (int i = tid; i < F0 * F1; i += 256) W1s[i] = W1[i];
    __syncthreads();

    int col = tid & 127;
    int rh  = tid >> 7;              // 0/1 -> rows rh*8 .. rh*8+7
    float bias = b1[col];

    int r0 = blockIdx.x * 16;        // 100000/16 = 6250 exact
    {
        int r = tid >> 4;
        int c = (tid & 15) * 4;
        *(float4*)&xs[r * F0 + c] = *(const float4*)&g_ag[(size_t)(r0 + r) * F0 + c];
    }
    __syncthreads();

    float acc[8];
    #pragma unroll
    for (int r = 0; r < 8; ++r) acc[r] = 0.0f;

    #pragma unroll
    for (int k = 0; k < F0; k += 4) {
        float w0 = W1s[(k + 0) * F1 + col];
        float w1 = W1s[(k + 1) * F1 + col];
        float w2 = W1s[(k + 2) * F1 + col];
        float w3 = W1s[(k + 3) * F1 + col];
        #pragma unroll
        for (int r = 0; r < 8; ++r) {
            float4 xv = *(const float4*)&xs[(rh * 8 + r) * F0 + k];
            acc[r] = fmaf(xv.x, w0, fmaf(xv.y, w1, fmaf(xv.z, w2, fmaf(xv.w, w3, acc[r]))));
        }
    }

    #pragma unroll
    for (int r = 0; r < 8; ++r) {
        int row = r0 + rh * 8 + r;
        g_h2[(size_t)row * F1 + col] = fmaxf(acc[r] + bias, 0.0f);
    }
}

// ---------------------------------------------------------------------------
// GEMM2: hs2 = (h2 @ W2) * dinv.  256 thr, 16 rows/tile.
// ---------------------------------------------------------------------------
__global__ void k_gemm2(const float* __restrict__ W2) {
    __shared__ float W2s[F1 * F2];       // 32 KB
    __shared__ float xs[16 * F1];        // 8 KB
    int tid = threadIdx.x;               // 256
    for (int i = tid; i < F1 * F2; i += 256) W2s[i] = W2[i];
    __syncthreads();

    int j = tid & 63;
    int q = tid >> 6;                    // 0..3 -> rows q*4 .. q*4+3

    int r0 = blockIdx.x * 16;            // 6250 exact
    #pragma unroll
    for (int t = 0; t < 2; ++t) {
        int f4 = tid + t * 256;          // 0..511
        int r  = f4 >> 5;                // 32 float4 per row
        int c  = (f4 & 31) * 4;
        *(float4*)&xs[r * F1 + c] = *(const float4*)&g_h2[(size_t)(r0 + r) * F1 + c];
    }
    __syncthreads();

    float acc[4] = {0.f, 0.f, 0.f, 0.f};
    #pragma unroll 8
    for (int k = 0; k < F1; k += 4) {
        float w0 = W2s[(k + 0) * F2 + j];
        float w1 = W2s[(k + 1) * F2 + j];
        float w2 = W2s[(k + 2) * F2 + j];
        float w3 = W2s[(k + 3) * F2 + j];
        #pragma unroll
        for (int r = 0; r < 4; ++r) {
            float4 xv = *(const float4*)&xs[(q * 4 + r) * F1 + k];
            acc[r] = fmaf(xv.x, w0, fmaf(xv.y, w1, fmaf(xv.z, w2, fmaf(xv.w, w3, acc[r]))));
        }
    }

    #pragma unroll
    for (int r = 0; r < 4; ++r) {
        int row = r0 + q * 4 + r;
        g_hs2[(size_t)row * F2 + j] = acc[r] * g_dinv[row];
    }
}

// ---------------------------------------------------------------------------
extern "C" void kernel_launch(void* const* d_in, const int* in_sizes, int n_in,
                              void* d_out, int out_size) {
    const float* x   = (const float*)d_in[0];
    const int*   ei  = (const int*)d_in[1];   // [2, E] int32
    const float* W1  = (const float*)d_in[2];
    const float* b1  = (const float*)d_in[3];
    const float* W2  = (const float*)d_in[4];
    const float* b2  = (const float*)d_in[5];
    float*       out = (float*)d_out;

    const int* src = ei;
    const int* dst = ei + N_EDGES;

    // degree + dinv + CSR
    k_deg_zero <<<(N_NODES + 255) / 256, 256>>>();
    k_deg_count<<<(N_EDGES + 255) / 256, 256>>>(dst);
    k_dinv     <<<(N_NODES + 255) / 256, 256>>>();
    k_scan_chunk<<<N_CHUNKS, 1024>>>();
    k_scan_sums<<<1, 128>>>();
    k_row_ptr  <<<(N_NODES + 255) / 256, 256>>>();
    k_csr_fill <<<(N_EDGES + 255) / 256, 256>>>(src, dst);

    // layer 1: prescale -> pull (64-dim) -> gemm(+bias+relu)
    k_prescale<<<(N_NODES * F0 / 4 + 255) / 256, 256>>>(x);
    k_pull1<<<(N_NODES * 16 + 255) / 256, 256>>>();           // half-warp per node
    k_gemm1<<<N_NODES / 16, 256>>>(W1, b1);

    // layer 2: gemm(*dinv) -> pull (64-dim, +bias)
    k_gemm2<<<N_NODES / 16, 256>>>(W2);
    k_pull2<<<(N_NODES * 16 + 255) / 256, 256>>>(b2, out);
}

// round 6
// speedup vs baseline: 4.8037x; 1.0029x over previous
#include <cuda_runtime.h>
#include <cuda_bf16.h>

#define N_NODES 100000
#define N_EDGES 3200000
#define F0 64
#define F1 128
#define F2 64
#define N_CHUNKS 98   // ceil(100000/1024)

// Scratch (static __device__ arrays)
__device__ int   g_degi[N_NODES];
__device__ int   g_scan[N_NODES];
__device__ int   g_chunksum[N_CHUNKS];
__device__ int   g_chunkoff[N_CHUNKS];
__device__ int   g_row [N_NODES + 1];
__device__ int   g_cur [N_NODES];
__device__ int   g_csr [N_EDGES];
__device__ float g_dinv[N_NODES];
__device__ float g_xs  [N_NODES * F0];  // x * dinv[node]  (pre-scaled input)
__device__ float g_ag  [N_NODES * F0];  // aggregated input-space features
__device__ float g_h2  [N_NODES * F1];  // relu'd layer-1 output
__device__ float g_hs2 [N_NODES * F2];  // (h2@W2) * dinv

// ---------------------------------------------------------------------------
// Degree histogram (int), dinv includes self-loop (+1).
// ---------------------------------------------------------------------------
__global__ void k_deg_zero() {
    int i = blockIdx.x * blockDim.x + threadIdx.x;
    if (i < N_NODES) g_degi[i] = 0;
}

__global__ void k_deg_count(const int* __restrict__ dst) {
    int e = blockIdx.x * blockDim.x + threadIdx.x;
    if (e < N_EDGES) atomicAdd(&g_degi[dst[e]], 1);
}

__global__ void k_dinv() {
    int i = blockIdx.x * blockDim.x + threadIdx.x;
    if (i < N_NODES) g_dinv[i] = rsqrtf((float)(g_degi[i] + 1));
}

// ---------------------------------------------------------------------------
// Prefix-sum -> row_ptr (exclusive), then CSR fill (by dst, storing src).
// ---------------------------------------------------------------------------
__global__ void k_scan_chunk() {   // grid N_CHUNKS, block 1024
    __shared__ int sh[1024];
    int gid = blockIdx.x * 1024 + threadIdx.x;
    int v = (gid < N_NODES) ? g_degi[gid] : 0;
    sh[threadIdx.x] = v;
    __syncthreads();
    #pragma unroll
    for (int off = 1; off < 1024; off <<= 1) {
        int t = (threadIdx.x >= off) ? sh[threadIdx.x - off] : 0;
        __syncthreads();
        sh[threadIdx.x] += t;
        __syncthreads();
    }
    if (gid < N_NODES) g_scan[gid] = sh[threadIdx.x];     // inclusive
    if (threadIdx.x == 1023) g_chunksum[blockIdx.x] = sh[1023];
}

__global__ void k_scan_sums() {    // 1 block, 128 threads
    __shared__ int sh[128];
    int tid = threadIdx.x;
    int v = (tid < N_CHUNKS) ? g_chunksum[tid] : 0;
    sh[tid] = v;
    __syncthreads();
    #pragma unroll
    for (int off = 1; off < 128; off <<= 1) {
        int t = (tid >= off) ? sh[tid - off] : 0;
        __syncthreads();
        sh[tid] += t;
        __syncthreads();
    }
    if (tid < N_CHUNKS) g_chunkoff[tid] = sh[tid] - v;    // exclusive
}

__global__ void k_row_ptr() {
    int i = blockIdx.x * blockDim.x + threadIdx.x;
    if (i < N_NODES) {
        int r = g_scan[i] - g_degi[i] + g_chunkoff[i >> 10];
        g_row[i] = r;
        g_cur[i] = r;
    }
    if (i == 0) g_row[N_NODES] = N_EDGES;
}

__global__ void k_csr_fill(const int* __restrict__ src, const int* __restrict__ dst) {
    int e = blockIdx.x * blockDim.x + threadIdx.x;
    if (e < N_EDGES) {
        int pos = atomicAdd(&g_cur[dst[e]], 1);
        g_csr[pos] = src[e];
    }
}

// ---------------------------------------------------------------------------
// Pre-scale: xs = x * dinv[node]
// ---------------------------------------------------------------------------
__global__ void k_prescale(const float* __restrict__ x) {
    int idx = blockIdx.x * blockDim.x + threadIdx.x;   // one float4 each
    if (idx < N_NODES * F0 / 4) {
        int i = idx >> 4;                              // 16 float4 per row
        float di = g_dinv[i];
        float4 a = *(const float4*)&x[(size_t)idx * 4];
        a.x *= di; a.y *= di; a.z *= di; a.w *= di;
        *(float4*)&g_xs[(size_t)idx * 4] = a;
    }
}

// ---------------------------------------------------------------------------
// Pull in 64-dim: half-warp per node, 4x unrolled gathers for MLP.
//   ag[node] = (xs[node] + sum_in xs[s]) * dinv[node]
// ---------------------------------------------------------------------------
__device__ __forceinline__ float4 pull64(const float* __restrict__ feat,
                                         int node, int sub, unsigned hmask) {
    int beg = g_row[node], end = g_row[node + 1];
    float4 acc = *(const float4*)&feat[(size_t)node * 64 + sub * 4];  // self-loop
    for (int e0 = beg; e0 < end; e0 += 16) {
        int n = end - e0;
        int s = (sub < n) ? g_csr[e0 + sub] : 0;
        int cnt = min(n, 16);
        int i = 0;
        for (; i + 4 <= cnt; i += 4) {
            int s0 = __shfl_sync(hmask, s, i + 0, 16);
            int s1 = __shfl_sync(hmask, s, i + 1, 16);
            int s2 = __shfl_sync(hmask, s, i + 2, 16);
            int s3 = __shfl_sync(hmask, s, i + 3, 16);
            float4 v0 = *(const float4*)&feat[(size_t)s0 * 64 + sub * 4];
            float4 v1 = *(const float4*)&feat[(size_t)s1 * 64 + sub * 4];
            float4 v2 = *(const float4*)&feat[(size_t)s2 * 64 + sub * 4];
            float4 v3 = *(const float4*)&feat[(size_t)s3 * 64 + sub * 4];
            acc.x += (v0.x + v1.x) + (v2.x + v3.x);
            acc.y += (v0.y + v1.y) + (v2.y + v3.y);
            acc.z += (v0.z + v1.z) + (v2.z + v3.z);
            acc.w += (v0.w + v1.w) + (v2.w + v3.w);
        }
        for (; i < cnt; ++i) {
            int ss = __shfl_sync(hmask, s, i, 16);
            float4 v = *(const float4*)&feat[(size_t)ss * 64 + sub * 4];
            acc.x += v.x; acc.y += v.y; acc.z += v.z; acc.w += v.w;
        }
    }
    return acc;
}

__global__ void k_pull1() {
    int lane = threadIdx.x & 31;
    int sub  = lane & 15;
    int half = lane >> 4;
    unsigned hmask = 0xFFFFu << (half * 16);
    int hw = (blockIdx.x * blockDim.x + threadIdx.x) >> 4;   // half-warp id
    int node = hw;
    if (node >= N_NODES) return;
    float4 acc = pull64(g_xs, node, sub, hmask);
    float di = g_dinv[node];
    acc.x *= di; acc.y *= di; acc.z *= di; acc.w *= di;
    *(float4*)&g_ag[(size_t)node * F0 + sub * 4] = acc;
}

__global__ void k_pull2(const float* __restrict__ b2, float* __restrict__ out) {
    int lane = threadIdx.x & 31;
    int sub  = lane & 15;
    int half = lane >> 4;
    unsigned hmask = 0xFFFFu << (half * 16);
    int hw = (blockIdx.x * blockDim.x + threadIdx.x) >> 4;
    int node = hw;
    if (node >= N_NODES) return;
    float4 acc = pull64(g_hs2, node, sub, hmask);
    float di = g_dinv[node];
    float4 bb = *(const float4*)&b2[sub * 4];
    float4 o;
    o.x = fmaf(acc.x, di, bb.x);
    o.y = fmaf(acc.y, di, bb.y);
    o.z = fmaf(acc.z, di, bb.z);
    o.w = fmaf(acc.w, di, bb.w);
    *(float4*)&out[(size_t)node * F2 + sub * 4] = o;
}

// ---------------------------------------------------------------------------
// GEMM1: h2 = relu(ag @ W1 + b1).  256 thr, 16 rows/tile.
// ---------------------------------------------------------------------------
__global__ void k_gemm1(const float* __restrict__ W1, const float* __restrict__ b1) {
    __shared__ float W1s[F0 * F1];   // 32 KB
    __shared__ float xs[16 * F0];    // 4 KB
    int tid = threadIdx.x;           // 256
    for (int i = tid; i < F0 * F1; i += 256) W1s[i] = W1[i];
    __syncthreads();

    int col = tid & 127;
    int rh  = tid >> 7;              // 0/1 -> rows rh*8 .. rh*8+7
    float bias = b1[col];

    int r0 = blockIdx.x * 16;        // 100000/16 = 6250 exact
    {
        int r = tid >> 4;
        int c = (tid & 15) * 4;
        *(float4*)&xs[r * F0 + c] = *(const float4*)&g_ag[(size_t)(r0 + r) * F0 + c];
    }
    __syncthreads();

    float acc[8];
    #pragma unroll
    for (int r = 0; r < 8; ++r) acc[r] = 0.0f;

    #pragma unroll
    for (int k = 0; k < F0; k += 4) {
        float w0 = W1s[(k + 0) * F1 + col];
        float w1 = W1s[(k + 1) * F1 + col];
        float w2 = W1s[(k + 2) * F1 + col];
        float w3 = W1s[(k + 3) * F1 + col];
        #pragma unroll
        for (int r = 0; r < 8; ++r) {
            float4 xv = *(const float4*)&xs[(rh * 8 + r) * F0 + k];
            acc[r] = fmaf(xv.x, w0, fmaf(xv.y, w1, fmaf(xv.z, w2, fmaf(xv.w, w3, acc[r]))));
        }
    }

    #pragma unroll
    for (int r = 0; r < 8; ++r) {
        int row = r0 + rh * 8 + r;
        g_h2[(size_t)row * F1 + col] = fmaxf(acc[r] + bias, 0.0f);
    }
}

// ---------------------------------------------------------------------------
// GEMM2: hs2 = (h2 @ W2) * dinv.  256 thr, 16 rows/tile.
// ---------------------------------------------------------------------------
__global__ void k_gemm2(const float* __restrict__ W2) {
    __shared__ float W2s[F1 * F2];       // 32 KB
    __shared__ float xs[16 * F1];        // 8 KB
    int tid = threadIdx.x;               // 256
    for (int i = tid; i < F1 * F2; i += 256) W2s[i] = W2[i];
    __syncthreads();

    int j = tid & 63;
    int q = tid >> 6;                    // 0..3 -> rows q*4 .. q*4+3

    int r0 = blockIdx.x * 16;            // 6250 exact
    #pragma unroll
    for (int t = 0; t < 2; ++t) {
        int f4 = tid + t * 256;          // 0..511
        int r  = f4 >> 5;                // 32 float4 per row
        int c  = (f4 & 31) * 4;
        *(float4*)&xs[r * F1 + c] = *(const float4*)&g_h2[(size_t)(r0 + r) * F1 + c];
    }
    __syncthreads();

    float acc[4] = {0.f, 0.f, 0.f, 0.f};
    #pragma unroll 8
    for (int k = 0; k < F1; k += 4) {
        float w0 = W2s[(k + 0) * F2 + j];
        float w1 = W2s[(k + 1) * F2 + j];
        float w2 = W2s[(k + 2) * F2 + j];
        float w3 = W2s[(k + 3) * F2 + j];
        #pragma unroll
        for (int r = 0; r < 4; ++r) {
            float4 xv = *(const float4*)&xs[(q * 4 + r) * F1 + k];
            acc[r] = fmaf(xv.x, w0, fmaf(xv.y, w1, fmaf(xv.z, w2, fmaf(xv.w, w3, acc[r]))));
        }
    }

    #pragma unroll
    for (int r = 0; r < 4; ++r) {
        int row = r0 + q * 4 + r;
        g_hs2[(size_t)row * F2 + j] = acc[r] * g_dinv[row];
    }
}

// ---------------------------------------------------------------------------
extern "C" void kernel_launch(void* const* d_in, const int* in_sizes, int n_in,
                              void* d_out, int out_size) {
    const float* x   = (const float*)d_in[0];
    const int*   ei  = (const int*)d_in[1];   // [2, E] int32
    const float* W1  = (const float*)d_in[2];
    const float* b1  = (const float*)d_in[3];
    const float* W2  = (const float*)d_in[4];
    const float* b2  = (const float*)d_in[5];
    float*       out = (float*)d_out;

    const int* src = ei;
    const int* dst = ei + N_EDGES;

    // degree + dinv + CSR
    k_deg_zero <<<(N_NODES + 255) / 256, 256>>>();
    k_deg_count<<<(N_EDGES + 255) / 256, 256>>>(dst);
    k_dinv     <<<(N_NODES + 255) / 256, 256>>>();
    k_scan_chunk<<<N_CHUNKS, 1024>>>();
    k_scan_sums<<<1, 128>>>();
    k_row_ptr  <<<(N_NODES + 255) / 256, 256>>>();
    k_csr_fill <<<(N_EDGES + 255) / 256, 256>>>(src, dst);

    // layer 1: prescale -> pull (64-dim) -> gemm(+bias+relu)
    k_prescale<<<(N_NODES * F0 / 4 + 255) / 256, 256>>>(x);
    k_pull1<<<(N_NODES * 16 + 255) / 256, 256>>>();           // half-warp per node
    k_gemm1<<<N_NODES / 16, 256>>>(W1, b1);

    // layer 2: gemm(*dinv) -> pull (64-dim, +bias)
    k_gemm2<<<N_NODES / 16, 256>>>(W2);
    k_pull2<<<(N_NODES * 16 + 255) / 256, 256>>>(b2, out);
}

// round 7
// speedup vs baseline: 6.0208x; 1.2534x over previous
#include <cuda_runtime.h>
#include <cuda_fp16.h>

#define N_NODES 100000
#define N_PAD   100032   // multiple of 64 (gemm1 tile) and 32 (gemm2 tile)
#define N_EDGES 3200000
#define F0 64
#define F1 128
#define F2 64
#define N_CHUNKS 98   // ceil(100000/1024); 98*1024=100352 >= N_PAD

// Scratch (static __device__ arrays)
__device__ int   g_degi[N_NODES];
__device__ int   g_scan[N_NODES];
__device__ int   g_chunksum[N_CHUNKS];
__device__ int   g_chunkoff[N_CHUNKS];
__device__ int   g_row [N_NODES + 1];
__device__ int   g_cur [N_NODES];
__device__ int   g_csr [N_EDGES];
__device__ float g_dinv[N_PAD];
__device__ uint2 g_xh  [N_NODES * 16];  // fp16: x * dinv[node]   (4 halves per uint2)
__device__ float g_ag  [N_PAD * F0];    // fp32 aggregated input-space features
__device__ float g_h2  [N_PAD * F1];    // fp32 relu'd layer-1 output
__device__ uint2 g_h2h [N_PAD * 16];    // fp16: (h2 @ W2) * dinv

// ---------------------------------------------------------------------------
// Degree histogram, CSR build
// ---------------------------------------------------------------------------
__global__ void k_deg_zero() {
    int i = blockIdx.x * blockDim.x + threadIdx.x;
    if (i < N_NODES) g_degi[i] = 0;
}

__global__ void k_deg_count(const int* __restrict__ dst) {
    int e = blockIdx.x * blockDim.x + threadIdx.x;
    if (e < N_EDGES) atomicAdd(&g_degi[dst[e]], 1);
}

__global__ void k_scan_chunk() {   // grid N_CHUNKS, block 1024; also writes dinv
    __shared__ int sh[1024];
    int gid = blockIdx.x * 1024 + threadIdx.x;
    int v = (gid < N_NODES) ? g_degi[gid] : 0;
    if (gid < N_PAD) g_dinv[gid] = rsqrtf((float)(v + 1));   // self-loop included
    sh[threadIdx.x] = v;
    __syncthreads();
    #pragma unroll
    for (int off = 1; off < 1024; off <<= 1) {
        int t = (threadIdx.x >= off) ? sh[threadIdx.x - off] : 0;
        __syncthreads();
        sh[threadIdx.x] += t;
        __syncthreads();
    }
    if (gid < N_NODES) g_scan[gid] = sh[threadIdx.x];     // inclusive
    if (threadIdx.x == 1023) g_chunksum[blockIdx.x] = sh[1023];
}

__global__ void k_scan_sums() {    // 1 block, 128 threads
    __shared__ int sh[128];
    int tid = threadIdx.x;
    int v = (tid < N_CHUNKS) ? g_chunksum[tid] : 0;
    sh[tid] = v;
    __syncthreads();
    #pragma unroll
    for (int off = 1; off < 128; off <<= 1) {
        int t = (tid >= off) ? sh[tid - off] : 0;
        __syncthreads();
        sh[tid] += t;
        __syncthreads();
    }
    if (tid < N_CHUNKS) g_chunkoff[tid] = sh[tid] - v;    // exclusive
}

__global__ void k_row_ptr() {
    int i = blockIdx.x * blockDim.x + threadIdx.x;
    if (i < N_NODES) {
        int r = g_scan[i] - g_degi[i] + g_chunkoff[i >> 10];
        g_row[i] = r;
        g_cur[i] = r;
    }
    if (i == 0) g_row[N_NODES] = N_EDGES;
}

__global__ void k_csr_fill(const int* __restrict__ src, const int* __restrict__ dst) {
    int e = blockIdx.x * blockDim.x + threadIdx.x;
    if (e < N_EDGES) {
        int pos = atomicAdd(&g_cur[dst[e]], 1);
        g_csr[pos] = src[e];
    }
}

// ---------------------------------------------------------------------------
// Pre-scale + fp16 pack: xh = half(x * dinv[node])
// ---------------------------------------------------------------------------
__device__ __forceinline__ unsigned pack2(float lo, float hi) {
    __half2 h = __floats2half2_rn(lo, hi);
    return *(unsigned*)&h;
}

__global__ void k_prescale(const float* __restrict__ x) {
    int idx = blockIdx.x * blockDim.x + threadIdx.x;   // one float4 -> one uint2
    if (idx < N_NODES * 16) {
        int i = idx >> 4;                              // 16 uint2 per row
        float di = g_dinv[i];
        float4 a = *(const float4*)&x[(size_t)idx * 4];
        g_xh[idx] = make_uint2(pack2(a.x * di, a.y * di), pack2(a.z * di, a.w * di));
    }
}

// ---------------------------------------------------------------------------
// Pull (64-dim, fp16 storage, fp32 accum): half-warp per node, MLP-4 gathers.
// ---------------------------------------------------------------------------
__device__ __forceinline__ void acc_u2(float4& acc, uint2 u) {
    float2 f0 = __half22float2(*(__half2*)&u.x);
    float2 f1 = __half22float2(*(__half2*)&u.y);
    acc.x += f0.x; acc.y += f0.y; acc.z += f1.x; acc.w += f1.y;
}

__device__ __forceinline__ float4 pull64h(const uint2* __restrict__ feat,
                                          int node, int sub, unsigned hmask) {
    int beg = g_row[node], end = g_row[node + 1];
    float4 acc = make_float4(0.f, 0.f, 0.f, 0.f);
    acc_u2(acc, feat[(size_t)node * 16 + sub]);        // self-loop
    for (int e0 = beg; e0 < end; e0 += 16) {
        int n = end - e0;
        int s = (sub < n) ? g_csr[e0 + sub] : 0;
        int cnt = min(n, 16);
        int i = 0;
        for (; i + 4 <= cnt; i += 4) {
            int s0 = __shfl_sync(hmask, s, i + 0, 16);
            int s1 = __shfl_sync(hmask, s, i + 1, 16);
            int s2 = __shfl_sync(hmask, s, i + 2, 16);
            int s3 = __shfl_sync(hmask, s, i + 3, 16);
            uint2 u0 = feat[(size_t)s0 * 16 + sub];
            uint2 u1 = feat[(size_t)s1 * 16 + sub];
            uint2 u2 = feat[(size_t)s2 * 16 + sub];
            uint2 u3 = feat[(size_t)s3 * 16 + sub];
            acc_u2(acc, u0); acc_u2(acc, u1); acc_u2(acc, u2); acc_u2(acc, u3);
        }
        for (; i < cnt; ++i) {
            int ss = __shfl_sync(hmask, s, i, 16);
            acc_u2(acc, feat[(size_t)ss * 16 + sub]);
        }
    }
    return acc;
}

__global__ void k_pull1() {
    int lane = threadIdx.x & 31;
    int sub  = lane & 15;
    unsigned hmask = 0xFFFFu << ((lane >> 4) * 16);
    int node = (blockIdx.x * blockDim.x + threadIdx.x) >> 4;
    if (node >= N_NODES) return;
    float4 acc = pull64h(g_xh, node, sub, hmask);
    float di = g_dinv[node];
    acc.x *= di; acc.y *= di; acc.z *= di; acc.w *= di;
    *(float4*)&g_ag[(size_t)node * F0 + sub * 4] = acc;
}

__global__ void k_pull2(const float* __restrict__ b2, float* __restrict__ out) {
    int lane = threadIdx.x & 31;
    int sub  = lane & 15;
    unsigned hmask = 0xFFFFu << ((lane >> 4) * 16);
    int node = (blockIdx.x * blockDim.x + threadIdx.x) >> 4;
    if (node >= N_NODES) return;
    float4 acc = pull64h(g_h2h, node, sub, hmask);
    float di = g_dinv[node];
    float4 bb = *(const float4*)&b2[sub * 4];
    float4 o;
    o.x = fmaf(acc.x, di, bb.x);
    o.y = fmaf(acc.y, di, bb.y);
    o.z = fmaf(acc.z, di, bb.z);
    o.w = fmaf(acc.w, di, bb.w);
    *(float4*)&out[(size_t)node * F2 + sub * 4] = o;
}

// ---------------------------------------------------------------------------
// GEMM1: h2 = relu(ag @ W1 + b1).  64-row x 128-col tile, 256 threads.
// Thread = (cg 0..31 -> 4 cols, rg 0..7 -> 8 rows). ~1.5 smem-B/FMA.
// ---------------------------------------------------------------------------
__device__ __forceinline__ void fma4(float4& a, float s, float4 w) {
    a.x = fmaf(s, w.x, a.x);
    a.y = fmaf(s, w.y, a.y);
    a.z = fmaf(s, w.z, a.z);
    a.w = fmaf(s, w.w, a.w);
}

__global__ void k_gemm1(const float* __restrict__ W1, const float* __restrict__ b1) {
    __shared__ float W1s[F0 * F1];   // 32 KB
    __shared__ float xs[64 * F0];    // 16 KB  (total 48 KB)
    int tid = threadIdx.x;           // 256
    for (int i = tid; i < F0 * F1; i += 256) W1s[i] = W1[i];

    int r0 = blockIdx.x * 64;
    #pragma unroll
    for (int t = 0; t < 4; ++t) {    // 1024 float4 loads of ag tile
        int f4 = tid + t * 256;
        int r  = f4 >> 4;            // 16 float4 per row
        int c  = (f4 & 15) * 4;
        *(float4*)&xs[r * F0 + c] = *(const float4*)&g_ag[(size_t)(r0 + r) * F0 + c];
    }
    __syncthreads();

    int cg = tid & 31;               // cols cg*4 .. cg*4+3
    int rg = tid >> 5;               // rows rg*8 .. rg*8+7

    float4 acc[8];
    #pragma unroll
    for (int r = 0; r < 8; ++r) acc[r] = make_float4(0.f, 0.f, 0.f, 0.f);

    #pragma unroll
    for (int k = 0; k < F0; k += 4) {
        float4 w0 = *(const float4*)&W1s[(k + 0) * F1 + cg * 4];
        float4 w1 = *(const float4*)&W1s[(k + 1) * F1 + cg * 4];
        float4 w2 = *(const float4*)&W1s[(k + 2) * F1 + cg * 4];
        float4 w3 = *(const float4*)&W1s[(k + 3) * F1 + cg * 4];
        #pragma unroll
        for (int r = 0; r < 8; ++r) {
            float4 xv = *(const float4*)&xs[(rg * 8 + r) * F0 + k];
            fma4(acc[r], xv.x, w0);
            fma4(acc[r], xv.y, w1);
            fma4(acc[r], xv.z, w2);
            fma4(acc[r], xv.w, w3);
        }
    }

    float4 bb = *(const float4*)&b1[cg * 4];
    #pragma unroll
    for (int r = 0; r < 8; ++r) {
        int row = r0 + rg * 8 + r;   // always < N_PAD
        float4 o;
        o.x = fmaxf(acc[r].x + bb.x, 0.0f);
        o.y = fmaxf(acc[r].y + bb.y, 0.0f);
        o.z = fmaxf(acc[r].z + bb.z, 0.0f);
        o.w = fmaxf(acc[r].w + bb.w, 0.0f);
        *(float4*)&g_h2[(size_t)row * F1 + cg * 4] = o;
    }
}

// ---------------------------------------------------------------------------
// GEMM2: h2h = half((h2 @ W2) * dinv).  32-row x 64-col tile, 256 threads.
// Thread = (cg 0..15 -> 4 cols, rg 0..15 -> 2 rows).
// ---------------------------------------------------------------------------
__global__ void k_gemm2(const float* __restrict__ W2) {
    __shared__ float W2s[F1 * F2];   // 32 KB
    __shared__ float xs[32 * F1];    // 16 KB  (total 48 KB)
    int tid = threadIdx.x;           // 256
    for (int i = tid; i < F1 * F2; i += 256) W2s[i] = W2[i];

    int r0 = blockIdx.x * 32;
    #pragma unroll
    for (int t = 0; t < 4; ++t) {    // 1024 float4 loads of h2 tile
        int f4 = tid + t * 256;
        int r  = f4 >> 5;            // 32 float4 per row
        int c  = (f4 & 31) * 4;
        *(float4*)&xs[r * F1 + c] = *(const float4*)&g_h2[(size_t)(r0 + r) * F1 + c];
    }
    __syncthreads();

    int cg = tid & 15;               // cols cg*4 .. cg*4+3
    int rg = tid >> 4;               // rows rg*2, rg*2+1

    float4 acc[2];
    acc[0] = make_float4(0.f, 0.f, 0.f, 0.f);
    acc[1] = make_float4(0.f, 0.f, 0.f, 0.f);

    #pragma unroll 8
    for (int k = 0; k < F1; k += 4) {
        float4 w0 = *(const float4*)&W2s[(k + 0) * F2 + cg * 4];
        float4 w1 = *(const float4*)&W2s[(k + 1) * F2 + cg * 4];
        float4 w2 = *(const float4*)&W2s[(k + 2) * F2 + cg * 4];
        float4 w3 = *(const float4*)&W2s[(k + 3) * F2 + cg * 4];
        #pragma unroll
        for (int r = 0; r < 2; ++r) {
            float4 xv = *(const float4*)&xs[(rg * 2 + r) * F1 + k];
            fma4(acc[r], xv.x, w0);
            fma4(acc[r], xv.y, w1);
            fma4(acc[r], xv.z, w2);
            fma4(acc[r], xv.w, w3);
        }
    }

    #pragma unroll
    for (int r = 0; r < 2; ++r) {
        int row = r0 + rg * 2 + r;   // always < N_PAD
        float di = g_dinv[row];
        g_h2h[(size_t)row * 16 + cg] =
            make_uint2(pack2(acc[r].x * di, acc[r].y * di),
                       pack2(acc[r].z * di, acc[r].w * di));
    }
}

// ---------------------------------------------------------------------------
extern "C" void kernel_launch(void* const* d_in, const int* in_sizes, int n_in,
                              void* d_out, int out_size) {
    const float* x   = (const float*)d_in[0];
    const int*   ei  = (const int*)d_in[1];   // [2, E] int32
    const float* W1  = (const float*)d_in[2];
    const float* b1  = (const float*)d_in[3];
    const float* W2  = (const float*)d_in[4];
    const float* b2  = (const float*)d_in[5];
    float*       out = (float*)d_out;

    const int* src = ei;
    const int* dst = ei + N_EDGES;

    // degree + dinv + CSR
    k_deg_zero <<<(N_NODES + 255) / 256, 256>>>();
    k_deg_count<<<(N_EDGES + 255) / 256, 256>>>(dst);
    k_scan_chunk<<<N_CHUNKS, 1024>>>();               // also computes dinv
    k_scan_sums<<<1, 128>>>();
    k_row_ptr  <<<(N_NODES + 255) / 256, 256>>>();
    k_csr_fill <<<(N_EDGES + 255) / 256, 256>>>(src, dst);

    // layer 1: prescale(fp16) -> pull(64-dim fp16) -> gemm(+bias+relu)
    k_prescale<<<(N_NODES * 16 + 255) / 256, 256>>>(x);
    k_pull1<<<(N_NODES * 16 + 255) / 256, 256>>>();
    k_gemm1<<<N_PAD / 64, 256>>>(W1, b1);

    // layer 2: gemm(*dinv -> fp16) -> pull(64-dim fp16, +bias)
    k_gemm2<<<N_PAD / 32, 256>>>(W2);
    k_pull2<<<(N_NODES * 16 + 255) / 256, 256>>>(b2, out);
}

// round 8
// speedup vs baseline: 7.2250x; 1.2000x over previous
#include <cuda_runtime.h>
#include <cuda_fp16.h>

#define N_NODES 100000
#define N_PAD   100032   // multiple of 64
#define N_EDGES 3200000
#define F0 64
#define F1 128
#define F2 64
#define N_CHUNKS 98   // ceil(100000/1024)

// Scratch (static __device__ arrays)
__device__ int   g_degi[N_NODES];
__device__ int   g_scan[N_NODES];
__device__ int   g_chunksum[N_CHUNKS];
__device__ int   g_chunkoff[N_CHUNKS];
__device__ int   g_row [N_NODES + 1];
__device__ int   g_cur [N_NODES];
__device__ int   g_csr [N_EDGES];
__device__ float g_dinv[N_PAD];
__device__ uint2 g_xh  [N_NODES * 16];  // fp16: x * dinv[node]
__device__ float g_ag  [N_PAD * F0];    // fp32 aggregated input-space features
__device__ float g_h2  [N_PAD * F1];    // fp32 relu'd layer-1 output
__device__ uint2 g_h2h [N_PAD * 16];    // fp16: (h2 @ W2) * dinv

// ---------------------------------------------------------------------------
// Degree histogram, CSR build
// ---------------------------------------------------------------------------
__global__ void k_deg_zero() {
    int i = blockIdx.x * blockDim.x + threadIdx.x;
    if (i < N_NODES) g_degi[i] = 0;
}

__global__ void k_deg_count(const int* __restrict__ dst) {
    int e = blockIdx.x * blockDim.x + threadIdx.x;
    if (e < N_EDGES) atomicAdd(&g_degi[dst[e]], 1);
}

__global__ void k_scan_chunk() {   // grid N_CHUNKS, block 1024; also writes dinv
    __shared__ int sh[1024];
    int gid = blockIdx.x * 1024 + threadIdx.x;
    int v = (gid < N_NODES) ? g_degi[gid] : 0;
    if (gid < N_PAD) g_dinv[gid] = rsqrtf((float)(v + 1));   // self-loop included
    sh[threadIdx.x] = v;
    __syncthreads();
    #pragma unroll
    for (int off = 1; off < 1024; off <<= 1) {
        int t = (threadIdx.x >= off) ? sh[threadIdx.x - off] : 0;
        __syncthreads();
        sh[threadIdx.x] += t;
        __syncthreads();
    }
    if (gid < N_NODES) g_scan[gid] = sh[threadIdx.x];     // inclusive
    if (threadIdx.x == 1023) g_chunksum[blockIdx.x] = sh[1023];
}

__global__ void k_scan_sums() {    // 1 block, 128 threads
    __shared__ int sh[128];
    int tid = threadIdx.x;
    int v = (tid < N_CHUNKS) ? g_chunksum[tid] : 0;
    sh[tid] = v;
    __syncthreads();
    #pragma unroll
    for (int off = 1; off < 128; off <<= 1) {
        int t = (tid >= off) ? sh[tid - off] : 0;
        __syncthreads();
        sh[tid] += t;
        __syncthreads();
    }
    if (tid < N_CHUNKS) g_chunkoff[tid] = sh[tid] - v;    // exclusive
}

__global__ void k_row_ptr() {
    int i = blockIdx.x * blockDim.x + threadIdx.x;
    if (i < N_NODES) {
        int r = g_scan[i] - g_degi[i] + g_chunkoff[i >> 10];
        g_row[i] = r;
        g_cur[i] = r;
    }
    if (i == 0) g_row[N_NODES] = N_EDGES;
}

__global__ void k_csr_fill(const int* __restrict__ src, const int* __restrict__ dst) {
    int e = blockIdx.x * blockDim.x + threadIdx.x;
    if (e < N_EDGES) {
        int pos = atomicAdd(&g_cur[dst[e]], 1);
        g_csr[pos] = src[e];
    }
}

// ---------------------------------------------------------------------------
// Pre-scale + fp16 pack: xh = half(x * dinv[node])
// ---------------------------------------------------------------------------
__device__ __forceinline__ unsigned pack2(float lo, float hi) {
    __half2 h = __floats2half2_rn(lo, hi);
    return *(unsigned*)&h;
}

__global__ void k_prescale(const float* __restrict__ x) {
    int idx = blockIdx.x * blockDim.x + threadIdx.x;
    if (idx < N_NODES * 16) {
        int i = idx >> 4;
        float di = g_dinv[i];
        float4 a = *(const float4*)&x[(size_t)idx * 4];
        g_xh[idx] = make_uint2(pack2(a.x * di, a.y * di), pack2(a.z * di, a.w * di));
    }
}

// ---------------------------------------------------------------------------
// Pull (64-dim fp16 storage, fp32 accum): half-warp per node, MLP-8 gathers.
// ---------------------------------------------------------------------------
__device__ __forceinline__ void acc_u2(float4& acc, uint2 u) {
    float2 f0 = __half22float2(*(__half2*)&u.x);
    float2 f1 = __half22float2(*(__half2*)&u.y);
    acc.x += f0.x; acc.y += f0.y; acc.z += f1.x; acc.w += f1.y;
}

__device__ __forceinline__ float4 pull64h(const uint2* __restrict__ feat,
                                          int node, int sub, unsigned hmask) {
    int beg = g_row[node], end = g_row[node + 1];
    float4 acc = make_float4(0.f, 0.f, 0.f, 0.f);
    acc_u2(acc, feat[(size_t)node * 16 + sub]);        // self-loop
    for (int e0 = beg; e0 < end; e0 += 16) {
        int n = end - e0;
        int s = (sub < n) ? g_csr[e0 + sub] : 0;
        int cnt = min(n, 16);
        int i = 0;
        for (; i + 8 <= cnt; i += 8) {
            uint2 u[8];
            #pragma unroll
            for (int j = 0; j < 8; ++j) {
                int ss = __shfl_sync(hmask, s, i + j, 16);
                u[j] = feat[(size_t)ss * 16 + sub];
            }
            #pragma unroll
            for (int j = 0; j < 8; ++j) acc_u2(acc, u[j]);
        }
        for (; i + 4 <= cnt; i += 4) {
            uint2 u[4];
            #pragma unroll
            for (int j = 0; j < 4; ++j) {
                int ss = __shfl_sync(hmask, s, i + j, 16);
                u[j] = feat[(size_t)ss * 16 + sub];
            }
            #pragma unroll
            for (int j = 0; j < 4; ++j) acc_u2(acc, u[j]);
        }
        for (; i < cnt; ++i) {
            int ss = __shfl_sync(hmask, s, i, 16);
            acc_u2(acc, feat[(size_t)ss * 16 + sub]);
        }
    }
    return acc;
}

__global__ void k_pull1() {
    int lane = threadIdx.x & 31;
    int sub  = lane & 15;
    unsigned hmask = 0xFFFFu << ((lane >> 4) * 16);
    int node = (blockIdx.x * blockDim.x + threadIdx.x) >> 4;
    if (node >= N_NODES) return;
    float4 acc = pull64h(g_xh, node, sub, hmask);
    float di = g_dinv[node];
    acc.x *= di; acc.y *= di; acc.z *= di; acc.w *= di;
    *(float4*)&g_ag[(size_t)node * F0 + sub * 4] = acc;
}

__global__ void k_pull2(const float* __restrict__ b2, float* __restrict__ out) {
    int lane = threadIdx.x & 31;
    int sub  = lane & 15;
    unsigned hmask = 0xFFFFu << ((lane >> 4) * 16);
    int node = (blockIdx.x * blockDim.x + threadIdx.x) >> 4;
    if (node >= N_NODES) return;
    float4 acc = pull64h(g_h2h, node, sub, hmask);
    float di = g_dinv[node];
    float4 bb = *(const float4*)&b2[sub * 4];
    float4 o;
    o.x = fmaf(acc.x, di, bb.x);
    o.y = fmaf(acc.y, di, bb.y);
    o.z = fmaf(acc.z, di, bb.z);
    o.w = fmaf(acc.w, di, bb.w);
    *(float4*)&out[(size_t)node * F2 + sub * 4] = o;
}

// ---------------------------------------------------------------------------
// tf32 helpers
// ---------------------------------------------------------------------------
__device__ __forceinline__ float tf32r(float f) {
    unsigned u;
    asm("cvt.rna.tf32.f32 %0, %1;" : "=r"(u) : "f"(f));
    return __uint_as_float(u);
}

__device__ __forceinline__ void mma_tf32(float c[4], unsigned a0, unsigned a1,
                                         unsigned a2, unsigned a3,
                                         unsigned b0, unsigned b1) {
    asm volatile(
        "mma.sync.aligned.m16n8k8.row.col.f32.tf32.tf32.f32 "
        "{%0,%1,%2,%3}, {%4,%5,%6,%7}, {%8,%9}, {%0,%1,%2,%3};"
        : "+f"(c[0]), "+f"(c[1]), "+f"(c[2]), "+f"(c[3])
        : "r"(a0), "r"(a1), "r"(a2), "r"(a3), "r"(b0), "r"(b1));
}

// ---------------------------------------------------------------------------
// GEMM1 (tensor): h2 = relu(ag @ W1 + b1).  Tile 64x128, K=64, 256 threads.
// smem: Wt [128][68] (n-major), As [64][68]; strides ≡4 mod 32 -> conflict-free.
// ---------------------------------------------------------------------------
#define G1_SMEM ((128 * 68 + 64 * 68) * 4)
__global__ void k_gemm1(const float* __restrict__ W1, const float* __restrict__ b1) {
    extern __shared__ float sm[];
    float* Wt = sm;              // [128][68]
    float* As = sm + 128 * 68;   // [64][68]
    int tid = threadIdx.x;       // 256

    for (int i = tid; i < F0 * F1; i += 256) {
        int k = i >> 7, n = i & 127;
        Wt[n * 68 + k] = tf32r(W1[i]);
    }
    int r0 = blockIdx.x * 64;
    #pragma unroll
    for (int t = 0; t < 4; ++t) {
        int f4 = tid + t * 256;
        int r = f4 >> 4, c = (f4 & 15) * 4;
        float4 v = *(const float4*)&g_ag[(size_t)(r0 + r) * F0 + c];
        As[r * 68 + c + 0] = tf32r(v.x);
        As[r * 68 + c + 1] = tf32r(v.y);
        As[r * 68 + c + 2] = tf32r(v.z);
        As[r * 68 + c + 3] = tf32r(v.w);
    }
    __syncthreads();

    int lane = tid & 31, warp = tid >> 5;
    int wr = (warp & 3) * 16;      // row offset within tile
    int wc = (warp >> 2) * 64;     // col offset
    int g = lane >> 2, tg = lane & 3;

    float c[8][4];
    #pragma unroll
    for (int nt = 0; nt < 8; ++nt)
        c[nt][0] = c[nt][1] = c[nt][2] = c[nt][3] = 0.f;

    #pragma unroll
    for (int ks = 0; ks < 8; ++ks) {
        int k0 = ks * 8 + tg;
        unsigned a0 = __float_as_uint(As[(wr + g    ) * 68 + k0]);
        unsigned a1 = __float_as_uint(As[(wr + g + 8) * 68 + k0]);
        unsigned a2 = __float_as_uint(As[(wr + g    ) * 68 + k0 + 4]);
        unsigned a3 = __float_as_uint(As[(wr + g + 8) * 68 + k0 + 4]);
        #pragma unroll
        for (int nt = 0; nt < 8; ++nt) {
            const float* bp = &Wt[(wc + nt * 8 + g) * 68 + k0];
            mma_tf32(c[nt], a0, a1, a2, a3,
                     __float_as_uint(bp[0]), __float_as_uint(bp[4]));
        }
    }

    #pragma unroll
    for (int nt = 0; nt < 8; ++nt) {
        int col = wc + nt * 8 + tg * 2;
        float2 bb = *(const float2*)&b1[col];
        int row = r0 + wr + g;
        float2 o0 = { fmaxf(c[nt][0] + bb.x, 0.f), fmaxf(c[nt][1] + bb.y, 0.f) };
        *(float2*)&g_h2[(size_t)row * F1 + col] = o0;
        float2 o1 = { fmaxf(c[nt][2] + bb.x, 0.f), fmaxf(c[nt][3] + bb.y, 0.f) };
        *(float2*)&g_h2[(size_t)(row + 8) * F1 + col] = o1;
    }
}

// ---------------------------------------------------------------------------
// GEMM2 (tensor): h2h = half((h2 @ W2) * dinv).  Tile 64x64, K=128.
// smem: Wt2 [64][132] (n-major), As2 [64][132].
// ---------------------------------------------------------------------------
#define G2_SMEM ((64 * 132 + 64 * 132) * 4)
__global__ void k_gemm2(const float* __restrict__ W2) {
    extern __shared__ float sm[];
    float* Wt = sm;              // [64][132]
    float* As = sm + 64 * 132;   // [64][132]
    int tid = threadIdx.x;       // 256

    for (int i = tid; i < F1 * F2; i += 256) {
        int k = i >> 6, n = i & 63;
        Wt[n * 132 + k] = tf32r(W2[i]);
    }
    int r0 = blockIdx.x * 64;
    #pragma unroll
    for (int t = 0; t < 8; ++t) {
        int f4 = tid + t * 256;
        int r = f4 >> 5, c = (f4 & 31) * 4;
        float4 v = *(const float4*)&g_h2[(size_t)(r0 + r) * F1 + c];
        As[r * 132 + c + 0] = tf32r(v.x);
        As[r * 132 + c + 1] = tf32r(v.y);
        As[r * 132 + c + 2] = tf32r(v.z);
        As[r * 132 + c + 3] = tf32r(v.w);
    }
    __syncthreads();

    int lane = tid & 31, warp = tid >> 5;
    int wr = (warp & 3) * 16;
    int wc = (warp >> 2) * 32;
    int g = lane >> 2, tg = lane & 3;

    float c[4][4];
    #pragma unroll
    for (int nt = 0; nt < 4; ++nt)
        c[nt][0] = c[nt][1] = c[nt][2] = c[nt][3] = 0.f;

    #pragma unroll
    for (int ks = 0; ks < 16; ++ks) {
        int k0 = ks * 8 + tg;
        unsigned a0 = __float_as_uint(As[(wr + g    ) * 132 + k0]);
        unsigned a1 = __float_as_uint(As[(wr + g + 8) * 132 + k0]);
        unsigned a2 = __float_as_uint(As[(wr + g    ) * 132 + k0 + 4]);
        unsigned a3 = __float_as_uint(As[(wr + g + 8) * 132 + k0 + 4]);
        #pragma unroll
        for (int nt = 0; nt < 4; ++nt) {
            const float* bp = &Wt[(wc + nt * 8 + g) * 132 + k0];
            mma_tf32(c[nt], a0, a1, a2, a3,
                     __float_as_uint(bp[0]), __float_as_uint(bp[4]));
        }
    }

    unsigned* h2u = (unsigned*)g_h2h;   // 32 uints per row
    #pragma unroll
    for (int nt = 0; nt < 4; ++nt) {
        int col = wc + nt * 8 + tg * 2;
        int row = r0 + wr + g;
        float d0 = g_dinv[row];
        h2u[(size_t)row * 32 + (col >> 1)] = pack2(c[nt][0] * d0, c[nt][1] * d0);
        float d1 = g_dinv[row + 8];
        h2u[(size_t)(row + 8) * 32 + (col >> 1)] = pack2(c[nt][2] * d1, c[nt][3] * d1);
    }
}

// ---------------------------------------------------------------------------
extern "C" void kernel_launch(void* const* d_in, const int* in_sizes, int n_in,
                              void* d_out, int out_size) {
    const float* x   = (const float*)d_in[0];
    const int*   ei  = (const int*)d_in[1];   // [2, E] int32
    const float* W1  = (const float*)d_in[2];
    const float* b1  = (const float*)d_in[3];
    const float* W2  = (const float*)d_in[4];
    const float* b2  = (const float*)d_in[5];
    float*       out = (float*)d_out;

    const int* src = ei;
    const int* dst = ei + N_EDGES;

    cudaFuncSetAttribute(k_gemm1, cudaFuncAttributeMaxDynamicSharedMemorySize, G1_SMEM);
    cudaFuncSetAttribute(k_gemm2, cudaFuncAttributeMaxDynamicSharedMemorySize, G2_SMEM);

    // degree + dinv + CSR
    k_deg_zero <<<(N_NODES + 255) / 256, 256>>>();
    k_deg_count<<<(N_EDGES + 255) / 256, 256>>>(dst);
    k_scan_chunk<<<N_CHUNKS, 1024>>>();               // also computes dinv
    k_scan_sums<<<1, 128>>>();
    k_row_ptr  <<<(N_NODES + 255) / 256, 256>>>();
    k_csr_fill <<<(N_EDGES + 255) / 256, 256>>>(src, dst);

    // layer 1: prescale(fp16) -> pull(64-dim fp16) -> tensor gemm(+bias+relu)
    k_prescale<<<(N_NODES * 16 + 255) / 256, 256>>>(x);
    k_pull1<<<(N_NODES * 16 + 255) / 256, 256>>>();
    k_gemm1<<<N_PAD / 64, 256, G1_SMEM>>>(W1, b1);

    // layer 2: tensor gemm(*dinv -> fp16) -> pull(64-dim fp16, +bias)
    k_gemm2<<<N_PAD / 64, 256, G2_SMEM>>>(W2);
    k_pull2<<<(N_NODES * 16 + 255) / 256, 256>>>(b2, out);
}